// round 2
// baseline (speedup 1.0000x reference)
#include <cuda_runtime.h>
#include <cstdio>

// ---------------------------------------------------------------------------
// Problem constants
// ---------------------------------------------------------------------------
#define BATCH 64
#define SEQ   512
#define DIM   768
#define BD    (BATCH * DIM)          // 49152 per entity
#define R192  (3 * BATCH)            // 192 batched rows
#define KDIM  (2 * DIM)              // 1536
#define PREDK (3 * DIM)              // 2304

// split-K factors
#define KS_FC1  6    // 1536 = 6 * 256
#define KS_GATE 4    // 1536 = 4 * 384
#define KS_PRED 8    // 2304 = 8 * 288

// ---------------------------------------------------------------------------
// Device scratch (no allocations allowed)
// ---------------------------------------------------------------------------
__device__ float g_ent [BATCH * PREDK];        // ent, (B,3,D) b-major == flat (B,3D)
__device__ float g_e0  [3 * BD];               // entity state ping
__device__ float g_e1  [3 * BD];               // entity state pong
__device__ float g_u   [3 * BD];               // u vectors
__device__ float g_X   [R192 * KDIM];          // assembled GEMM input
__device__ float g_part[KS_FC1 * R192 * 512];  // 589824 floats, reused by all GEMMs

// ---------------------------------------------------------------------------
// f32x2 packed-FMA helpers (sm_100a: doubles FFMA throughput vs 3-reg FFMA)
// ---------------------------------------------------------------------------
__device__ __forceinline__ unsigned long long pack2(float x, float y) {
    unsigned long long r;
    asm("mov.b64 %0, {%1, %2};" : "=l"(r) : "f"(x), "f"(y));
    return r;
}
__device__ __forceinline__ void ffma2(unsigned long long& acc,
                                      unsigned long long a,
                                      unsigned long long b) {
    asm("fma.rn.f32x2 %0, %1, %2, %3;" : "=l"(acc) : "l"(a), "l"(b), "l"(acc));
}
__device__ __forceinline__ float2 unpack2(unsigned long long v) {
    float2 f;
    asm("mov.b64 {%0, %1}, %2;" : "=f"(f.x), "=f"(f.y) : "l"(v));
    return f;
}
__device__ __forceinline__ float sigmoidf(float x) {
    return 1.0f / (1.0f + expf(-x));
}

// ---------------------------------------------------------------------------
// Kernel 1: span max-pool + entity score (sigmoid(ent @ proj_W + proj_b))
// one block per (b, k) pair; 256 threads, 3 columns per thread
// ---------------------------------------------------------------------------
__global__ void __launch_bounds__(256)
maxpool_kernel(const float* __restrict__ enc, const int* __restrict__ ep,
               const float* __restrict__ projW, const float* __restrict__ projb,
               float* __restrict__ ent, float* __restrict__ e0,
               float* __restrict__ out_score)
{
    int bk = blockIdx.x;                 // 0..191
    int b = bk / 3, k = bk - b * 3;
    int t = threadIdx.x;

    int s0 = ep[bk * 2 + 0];
    int s1 = ep[bk * 2 + 1];

    float m0 = -1e30f, m1 = -1e30f, m2 = -1e30f;
    const float* base = enc + (size_t)b * SEQ * DIM;
    #pragma unroll 4
    for (int s = s0; s <= s1; s++) {
        const float* row = base + s * DIM;
        m0 = fmaxf(m0, row[t]);
        m1 = fmaxf(m1, row[t + 256]);
        m2 = fmaxf(m2, row[t + 512]);
    }

    // ent (B,3,D) b-major (also serves as flat (B,3D) for pred head)
    float* ep_out = ent + b * PREDK + k * DIM;
    ep_out[t]       = m0;
    ep_out[t + 256] = m1;
    ep_out[t + 512] = m2;
    // entity state layout: [p * BD + b * DIM + d]
    float* e0_out = e0 + k * BD + b * DIM;
    e0_out[t]       = m0;
    e0_out[t + 256] = m1;
    e0_out[t + 512] = m2;

    // proj score: dot over 768 + bias, sigmoid
    float loc = m0 * projW[t] + m1 * projW[t + 256] + m2 * projW[t + 512];
    __shared__ float red[256];
    red[t] = loc;
    __syncthreads();
    for (int off = 128; off > 0; off >>= 1) {
        if (t < off) red[t] += red[t + off];
        __syncthreads();
    }
    if (t == 0) out_score[bk] = sigmoidf(red[0] + projb[0]);
}

// ---------------------------------------------------------------------------
// Kernel 2: split-K partial GEMM.  P[z][m][n] = sum_{k in chunk z} A[m][k] W[k][n]
// A row-major (lda), W row-major (K x N). Tile 64x64x32, 256 thr, 4x4 f32x2.
// Deterministic: no atomics; partials reduced later in fixed order.
// ---------------------------------------------------------------------------
#define BM 64
#define BN 64
#define BKT 32

__global__ void __launch_bounds__(256)
gemm_part_kernel(const float* __restrict__ A, int lda,
                 const float* __restrict__ W, int N,
                 float* __restrict__ P, int MN, int kchunk)
{
    __shared__ float As[BKT][BM + 4];
    __shared__ float Bs[BKT][BN + 4];

    int tid = threadIdx.x;
    int n0 = blockIdx.x * BN;
    int m0 = blockIdx.y * BM;
    int k0 = blockIdx.z * kchunk;

    int tx = tid & 15;        // N dir, 4 cols
    int ty = tid >> 4;        // M dir, 4 rows

    int arow = tid >> 2;              // 0..63
    int aqc  = (tid & 3) * 4;         // 0,4,8,12
    int brow = tid >> 3;              // 0..31
    int bqc  = (tid & 7) * 4;         // 0..28

    unsigned long long acc[4][2];
    #pragma unroll
    for (int i = 0; i < 4; i++) { acc[i][0] = 0ULL; acc[i][1] = 0ULL; }

    const float* ap = A + (size_t)(m0 + arow) * lda + k0;

    for (int kb = 0; kb < kchunk; kb += BKT) {
        float4 a0 = *(const float4*)(ap + kb + aqc);
        float4 a1 = *(const float4*)(ap + kb + aqc + 16);
        const float* wp = W + (size_t)(k0 + kb + brow) * N + n0;
        float4 b0 = *(const float4*)(wp + bqc);
        float4 b1 = *(const float4*)(wp + bqc + 32);

        __syncthreads();   // previous tile's compute done
        As[aqc + 0][arow] = a0.x;  As[aqc + 1][arow] = a0.y;
        As[aqc + 2][arow] = a0.z;  As[aqc + 3][arow] = a0.w;
        As[aqc + 16][arow] = a1.x; As[aqc + 17][arow] = a1.y;
        As[aqc + 18][arow] = a1.z; As[aqc + 19][arow] = a1.w;
        *(float4*)&Bs[brow][bqc]      = b0;
        *(float4*)&Bs[brow][bqc + 32] = b1;
        __syncthreads();

        #pragma unroll
        for (int kk = 0; kk < BKT; kk++) {
            float4 av = *(const float4*)&As[kk][ty * 4];
            float4 bv = *(const float4*)&Bs[kk][tx * 4];
            unsigned long long b01 = pack2(bv.x, bv.y);
            unsigned long long b23 = pack2(bv.z, bv.w);
            unsigned long long am;
            am = pack2(av.x, av.x); ffma2(acc[0][0], am, b01); ffma2(acc[0][1], am, b23);
            am = pack2(av.y, av.y); ffma2(acc[1][0], am, b01); ffma2(acc[1][1], am, b23);
            am = pack2(av.z, av.z); ffma2(acc[2][0], am, b01); ffma2(acc[2][1], am, b23);
            am = pack2(av.w, av.w); ffma2(acc[3][0], am, b01); ffma2(acc[3][1], am, b23);
        }
    }

    float* pp = P + (size_t)blockIdx.z * MN;
    #pragma unroll
    for (int m = 0; m < 4; m++) {
        float2 c0 = unpack2(acc[m][0]);
        float2 c1 = unpack2(acc[m][1]);
        float4 v = make_float4(c0.x, c0.y, c1.x, c1.y);
        *(float4*)(pp + (size_t)(m0 + ty * 4 + m) * N + n0 + tx * 4) = v;
    }
}

// ---------------------------------------------------------------------------
// Kernel 3: assemble X for vr fc1: row r=p*64+b: [e_A(p)[b] | e_B(p)[b]]
// pairs: p0:(e2,e3)  p1:(e1,e3)  p2:(e1,e2)
// ---------------------------------------------------------------------------
__global__ void __launch_bounds__(256)
asm_fc1_kernel(const float* __restrict__ e_cur, float* __restrict__ X)
{
    const int SA[3] = {1, 0, 0};
    const int SB[3] = {2, 2, 1};
    int idx = blockIdx.x * 256 + threadIdx.x;        // float4 index
    if (idx >= R192 * KDIM / 4) return;
    int c4 = idx % (KDIM / 4);                       // 0..383
    int r  = idx / (KDIM / 4);
    int p = r >> 6, b = r & 63;
    float4 v;
    if (c4 < DIM / 4)
        v = *(const float4*)(e_cur + SA[p] * BD + b * DIM + c4 * 4);
    else
        v = *(const float4*)(e_cur + SB[p] * BD + b * DIM + (c4 - DIM / 4) * 4);
    *(float4*)(X + (size_t)r * KDIM + c4 * 4) = v;
}

// ---------------------------------------------------------------------------
// Kernel 4: fc1 finish + fc2 + Ar projection + u = a * e
// one block per row r (192 blocks)
// ---------------------------------------------------------------------------
__global__ void __launch_bounds__(256)
fc1_finish_kernel(const float* __restrict__ P, const float* __restrict__ b1,
                  const float* __restrict__ W2, const float* __restrict__ b2,
                  const float* __restrict__ ArW, const float* __restrict__ Arb,
                  const float* __restrict__ e_cur, float* __restrict__ u)
{
    __shared__ float sh_h[512];
    __shared__ float red[5][256];
    __shared__ float sh_s[5];
    int r = blockIdx.x, t = threadIdx.x;
    int p = r >> 6, b = r & 63;
    const int MN = R192 * 512;

    for (int j = t; j < 512; j += 256) {
        float s = b1[j];
        #pragma unroll
        for (int ss = 0; ss < KS_FC1; ss++) s += P[ss * MN + r * 512 + j];
        sh_h[j] = fmaxf(s, 0.0f);
    }
    __syncthreads();

    float ps[5] = {0, 0, 0, 0, 0};
    for (int j = t; j < 512; j += 256) {
        float h = sh_h[j];
        #pragma unroll
        for (int c = 0; c < 5; c++) ps[c] += h * W2[j * 5 + c];
    }
    #pragma unroll
    for (int c = 0; c < 5; c++) red[c][t] = ps[c];
    __syncthreads();
    for (int off = 128; off > 0; off >>= 1) {
        if (t < off) {
            #pragma unroll
            for (int c = 0; c < 5; c++) red[c][t] += red[c][t + off];
        }
        __syncthreads();
    }
    if (t < 5) sh_s[t] = sigmoidf(red[t][0] + b2[t]);
    __syncthreads();

    float s0 = sh_s[0], s1 = sh_s[1], s2 = sh_s[2], s3 = sh_s[3], s4 = sh_s[4];
    const float* epv = e_cur + p * BD + b * DIM;
    float* up = u + p * BD + b * DIM;
    for (int d = t; d < DIM; d += 256) {
        float a = Arb[d] + s0 * ArW[d] + s1 * ArW[DIM + d] + s2 * ArW[2 * DIM + d]
                + s3 * ArW[3 * DIM + d] + s4 * ArW[4 * DIM + d];
        up[d] = a * epv[d];
    }
}

// ---------------------------------------------------------------------------
// Kernel 5: assemble X for gate: row r: [u_p[b] | e_p[b]]
// ---------------------------------------------------------------------------
__global__ void __launch_bounds__(256)
asm_gate_kernel(const float* __restrict__ u, const float* __restrict__ e_cur,
                float* __restrict__ X)
{
    int idx = blockIdx.x * 256 + threadIdx.x;
    if (idx >= R192 * KDIM / 4) return;
    int c4 = idx % (KDIM / 4);
    int r  = idx / (KDIM / 4);
    int p = r >> 6, b = r & 63;
    float4 v;
    if (c4 < DIM / 4)
        v = *(const float4*)(u + p * BD + b * DIM + c4 * 4);
    else
        v = *(const float4*)(e_cur + p * BD + b * DIM + (c4 - DIM / 4) * 4);
    *(float4*)(X + (size_t)r * KDIM + c4 * 4) = v;
}

// ---------------------------------------------------------------------------
// Kernel 6: gate finish: g = sigmoid(sum partials + bias); e_next = g*e + (1-g)*u
// ---------------------------------------------------------------------------
__global__ void __launch_bounds__(256)
gate_finish_kernel(const float* __restrict__ P, const float* __restrict__ gb,
                   const float* __restrict__ e_cur, const float* __restrict__ u,
                   float* __restrict__ e_next)
{
    int idx = blockIdx.x * 256 + threadIdx.x;      // < 192*768
    if (idx >= R192 * DIM) return;
    const int MN = R192 * DIM;
    int r = idx / DIM, n = idx - r * DIM;
    int p = r >> 6, b = r & 63;
    float s = gb[n];
    #pragma unroll
    for (int ss = 0; ss < KS_GATE; ss++) s += P[ss * MN + idx];
    float g = sigmoidf(s);
    int off = p * BD + b * DIM + n;
    e_next[off] = g * e_cur[off] + (1.0f - g) * u[off];
}

// ---------------------------------------------------------------------------
// Kernel 7: pred finish: relu(partials+b1) @ W2 + b2 -> rel (B,5), no activation
// one block per batch row
// ---------------------------------------------------------------------------
__global__ void __launch_bounds__(256)
pred_finish_kernel(const float* __restrict__ P, const float* __restrict__ b1,
                   const float* __restrict__ W2, const float* __restrict__ b2,
                   float* __restrict__ rel_out)
{
    __shared__ float sh_h[512];
    __shared__ float red[5][256];
    int b = blockIdx.x, t = threadIdx.x;
    const int MN = BATCH * 512;

    for (int j = t; j < 512; j += 256) {
        float s = b1[j];
        #pragma unroll
        for (int ss = 0; ss < KS_PRED; ss++) s += P[ss * MN + b * 512 + j];
        sh_h[j] = fmaxf(s, 0.0f);
    }
    __syncthreads();

    float ps[5] = {0, 0, 0, 0, 0};
    for (int j = t; j < 512; j += 256) {
        float h = sh_h[j];
        #pragma unroll
        for (int c = 0; c < 5; c++) ps[c] += h * W2[j * 5 + c];
    }
    #pragma unroll
    for (int c = 0; c < 5; c++) red[c][t] = ps[c];
    __syncthreads();
    for (int off = 128; off > 0; off >>= 1) {
        if (t < off) {
            #pragma unroll
            for (int c = 0; c < 5; c++) red[c][t] += red[c][t + off];
        }
        __syncthreads();
    }
    if (t < 5) rel_out[b * 5 + t] = red[t][0] + b2[t];
}

// ---------------------------------------------------------------------------
// Kernel 8: final_ent copy: out[b][p][d] = e_final[p][b][d]
// ---------------------------------------------------------------------------
__global__ void __launch_bounds__(256)
final_copy_kernel(const float* __restrict__ e_final, float* __restrict__ out)
{
    int idx = blockIdx.x * 256 + threadIdx.x;
    if (idx >= 3 * BD) return;
    int p = idx / BD;
    int rem = idx - p * BD;
    int b = rem / DIM;
    int d = rem - b * DIM;
    out[b * PREDK + p * DIM + d] = e_final[idx];
}

// ---------------------------------------------------------------------------
// Launcher
// ---------------------------------------------------------------------------
extern "C" void kernel_launch(void* const* d_in, const int* in_sizes, int n_in,
                              void* d_out, int out_size)
{
    const float* encoding = (const float*)d_in[0];
    const int*   ent_pos  = (const int*)  d_in[1];
    const float* Ar_W     = (const float*)d_in[2];
    const float* Ar_b     = (const float*)d_in[3];
    const float* Vr_W1    = (const float*)d_in[4];
    const float* Vr_b1    = (const float*)d_in[5];
    const float* Vr_W2    = (const float*)d_in[6];
    const float* Vr_b2    = (const float*)d_in[7];
    const float* gate_W   = (const float*)d_in[8];
    const float* gate_b   = (const float*)d_in[9];
    const float* pred_W1  = (const float*)d_in[10];
    const float* pred_b1  = (const float*)d_in[11];
    const float* pred_W2  = (const float*)d_in[12];
    const float* pred_b2  = (const float*)d_in[13];
    const float* proj_W   = (const float*)d_in[14];
    const float* proj_b   = (const float*)d_in[15];

    float* out = (float*)d_out;
    float* out_rel   = out;              // (64,5)  -> 320
    float* out_score = out + 320;        // (64,3)  -> 192
    float* out_final = out + 512;        // (64,3,768)

    float *p_ent, *p_e0, *p_e1, *p_u, *p_X, *p_part;
    cudaGetSymbolAddress((void**)&p_ent,  g_ent);
    cudaGetSymbolAddress((void**)&p_e0,   g_e0);
    cudaGetSymbolAddress((void**)&p_e1,   g_e1);
    cudaGetSymbolAddress((void**)&p_u,    g_u);
    cudaGetSymbolAddress((void**)&p_X,    g_X);
    cudaGetSymbolAddress((void**)&p_part, g_part);

    // 1. span max-pool + entity scores (+ init entity state e0)
    maxpool_kernel<<<R192, 256>>>(encoding, ent_pos, proj_W, proj_b,
                                  p_ent, p_e0, out_score);

    // 2. pred head (depends only on ent): M=64, K=2304, N=512, KS=8 (chunk 288)
    gemm_part_kernel<<<dim3(512 / BN, 1, KS_PRED), 256>>>(
        p_ent, PREDK, pred_W1, 512, p_part, BATCH * 512, PREDK / KS_PRED);
    pred_finish_kernel<<<BATCH, 256>>>(p_part, pred_b1, pred_W2, pred_b2, out_rel);

    // 3. five message-passing iterations (ping-pong e0 <-> e1)
    for (int it = 0; it < 5; it++) {
        float* e_cur  = (it & 1) ? p_e1 : p_e0;
        float* e_next = (it & 1) ? p_e0 : p_e1;

        // vr fc1: M=192, K=1536, N=512
        asm_fc1_kernel<<<(R192 * KDIM / 4 + 255) / 256, 256>>>(e_cur, p_X);
        gemm_part_kernel<<<dim3(512 / BN, R192 / BM, KS_FC1), 256>>>(
            p_X, KDIM, Vr_W1, 512, p_part, R192 * 512, KDIM / KS_FC1);
        fc1_finish_kernel<<<R192, 256>>>(p_part, Vr_b1, Vr_W2, Vr_b2,
                                         Ar_W, Ar_b, e_cur, p_u);

        // gate: M=192, K=1536, N=768
        asm_gate_kernel<<<(R192 * KDIM / 4 + 255) / 256, 256>>>(p_u, e_cur, p_X);
        gemm_part_kernel<<<dim3(768 / BN, R192 / BM, KS_GATE), 256>>>(
            p_X, KDIM, gate_W, 768, p_part, R192 * DIM, KDIM / KS_GATE);
        gate_finish_kernel<<<(R192 * DIM + 255) / 256, 256>>>(
            p_part, gate_b, e_cur, p_u, e_next);
    }

    // after 5 iterations the result lives in e1 (odd count)
    final_copy_kernel<<<(3 * BD + 255) / 256, 256>>>(p_e1, out_final);

    (void)in_sizes; (void)n_in; (void)out_size;
}